// round 1
// baseline (speedup 1.0000x reference)
#include <cuda_runtime.h>

#define N_NODES 50000
#define N_EDGES 1600000
#define E_TOT   (N_EDGES + N_NODES)
#define IN_C    256
#define HID_C   128
#define OUT_C   16
#define HEADS   8

// ---------------- scratch (device globals; no allocation allowed) ------------
__device__ __align__(256) float g_h1[N_NODES * HID_C];
__device__ __align__(256) float g_asrc1[N_NODES * HEADS];
__device__ __align__(256) float g_adst1[N_NODES * HEADS];
__device__ __align__(256) float g_amax1[N_NODES * HEADS];
__device__ __align__(256) float g_denom1[N_NODES * HEADS];
__device__ __align__(256) float g_accum1[N_NODES * HID_C];
__device__ __align__(256) float g_hrelu[N_NODES * HID_C];
__device__ __align__(256) float g_h2[N_NODES * OUT_C];
__device__ __align__(256) float g_asrc2[N_NODES];
__device__ __align__(256) float g_adst2[N_NODES];
__device__ __align__(256) float g_amax2[N_NODES];
__device__ __align__(256) float g_denom2[N_NODES];
__device__ __align__(256) float g_accum2[N_NODES * OUT_C];

// ---------------- helpers ----------------------------------------------------
__device__ __forceinline__ void atomicMaxF(float* addr, float v) {
    // order-preserving float max via int/uint atomics
    if (v >= 0.0f) atomicMax((int*)addr, __float_as_int(v));
    else           atomicMin((unsigned int*)addr, __float_as_uint(v));
}

__device__ __forceinline__ void red_add_v4(float* p, float4 v) {
    asm volatile("red.global.add.v4.f32 [%0], {%1, %2, %3, %4};"
                 :: "l"(p), "f"(v.x), "f"(v.y), "f"(v.z), "f"(v.w)
                 : "memory");
}

__device__ __forceinline__ float lrelu(float a) {
    return a > 0.0f ? a : 0.2f * a;
}

// ---------------- init: zero accumulators, -inf maxima -----------------------
__global__ void init_kernel() {
    int i = blockIdx.x * blockDim.x + threadIdx.x;
    int stride = gridDim.x * blockDim.x;
    const float NEG = __int_as_float(0xff800000);
    for (int j = i; j < N_NODES * HID_C; j += stride) g_accum1[j] = 0.0f;
    for (int j = i; j < N_NODES * HEADS; j += stride) { g_denom1[j] = 0.0f; g_amax1[j] = NEG; }
    for (int j = i; j < N_NODES * OUT_C; j += stride) g_accum2[j] = 0.0f;
    for (int j = i; j < N_NODES; j += stride) { g_denom2[j] = 0.0f; g_amax2[j] = NEG; }
}

// ---------------- GEMM1: h1 = x @ W1  (50000x256 @ 256x128) ------------------
// BM=128 BN=128 BK=8 TM=8 TN=8, 256 threads
__global__ __launch_bounds__(256) void gemm1_kernel(const float* __restrict__ A,
                                                    const float* __restrict__ B) {
    __shared__ float As[8][128];
    __shared__ float Bs[8][128];
    const int M = N_NODES, N = 128, K = 256;
    int rowBase = blockIdx.x * 128;
    int tid = threadIdx.x;
    int trow = tid >> 4;          // 0..15
    int tcol = tid & 15;          // 0..15
    float acc[8][8] = {};
    int aRow = tid >> 1;          // 0..127
    int aCol = (tid & 1) * 4;     // 0 or 4
    int bRow = tid >> 5;          // 0..7
    int bCol = (tid & 31) * 4;    // 0..124

    for (int k0 = 0; k0 < K; k0 += 8) {
        float4 av = make_float4(0.f, 0.f, 0.f, 0.f);
        int gr = rowBase + aRow;
        if (gr < M) av = *(const float4*)&A[(long)gr * K + k0 + aCol];
        As[aCol + 0][aRow] = av.x;
        As[aCol + 1][aRow] = av.y;
        As[aCol + 2][aRow] = av.z;
        As[aCol + 3][aRow] = av.w;
        *(float4*)&Bs[bRow][bCol] = *(const float4*)&B[(k0 + bRow) * N + bCol];
        __syncthreads();
#pragma unroll
        for (int k = 0; k < 8; k++) {
            float ra[8], rb[8];
#pragma unroll
            for (int i = 0; i < 8; i++) ra[i] = As[k][trow * 8 + i];
#pragma unroll
            for (int j = 0; j < 8; j++) rb[j] = Bs[k][tcol * 8 + j];
#pragma unroll
            for (int i = 0; i < 8; i++)
#pragma unroll
                for (int j = 0; j < 8; j++) acc[i][j] += ra[i] * rb[j];
        }
        __syncthreads();
    }
#pragma unroll
    for (int i = 0; i < 8; i++) {
        int r = rowBase + trow * 8 + i;
        if (r < M) {
#pragma unroll
            for (int j = 0; j < 8; j += 4) {
                float4 v = make_float4(acc[i][j], acc[i][j + 1], acc[i][j + 2], acc[i][j + 3]);
                *(float4*)&g_h1[r * 128 + tcol * 8 + j] = v;
            }
        }
    }
}

// ---------------- a_src1 / a_dst1 per node (warp per node) -------------------
__global__ void att1_kernel(const float* __restrict__ att_s,
                            const float* __restrict__ att_d) {
    int w = (blockIdx.x * blockDim.x + threadIdx.x) >> 5;
    int lane = threadIdx.x & 31;
    if (w >= N_NODES) return;
    int h = lane >> 2, q = lane & 3;
    float4 hv = *(const float4*)&g_h1[w * 128 + lane * 4];
    float4 as = *(const float4*)&att_s[h * 16 + q * 4];
    float4 ad = *(const float4*)&att_d[h * 16 + q * 4];
    float ps = hv.x * as.x + hv.y * as.y + hv.z * as.z + hv.w * as.w;
    float pd = hv.x * ad.x + hv.y * ad.y + hv.z * ad.z + hv.w * ad.w;
    ps += __shfl_xor_sync(0xffffffffu, ps, 1);
    ps += __shfl_xor_sync(0xffffffffu, ps, 2);
    pd += __shfl_xor_sync(0xffffffffu, pd, 1);
    pd += __shfl_xor_sync(0xffffffffu, pd, 2);
    if (q == 0) {
        g_asrc1[w * 8 + h] = ps;
        g_adst1[w * 8 + h] = pd;
    }
}

// ---------------- layer1 edge pass A: segment max ----------------------------
__global__ void edgeA1_kernel(const int* __restrict__ src, const int* __restrict__ dst) {
    int e = blockIdx.x * blockDim.x + threadIdx.x;
    if (e >= E_TOT) return;
    int s, d;
    if (e < N_EDGES) { s = src[e]; d = dst[e]; }
    else             { s = d = e - N_EDGES; }
    float4 s0 = *(const float4*)&g_asrc1[s * 8];
    float4 s1 = *(const float4*)&g_asrc1[s * 8 + 4];
    float4 d0 = *(const float4*)&g_adst1[d * 8];
    float4 d1 = *(const float4*)&g_adst1[d * 8 + 4];
    float al[8] = { s0.x + d0.x, s0.y + d0.y, s0.z + d0.z, s0.w + d0.w,
                    s1.x + d1.x, s1.y + d1.y, s1.z + d1.z, s1.w + d1.w };
#pragma unroll
    for (int h = 0; h < 8; h++) atomicMaxF(&g_amax1[d * 8 + h], lrelu(al[h]));
}

// ---------------- layer1 edge pass B: exp, denom, weighted message -----------
// warp per edge; lane l -> channels 4l..4l+3, head l>>2
__global__ void edgeB1_kernel(const int* __restrict__ src, const int* __restrict__ dst) {
    int gw = (blockIdx.x * blockDim.x + threadIdx.x) >> 5;
    int lane = threadIdx.x & 31;
    if (gw >= E_TOT) return;
    int s, d;
    if (gw < N_EDGES) { s = src[gw]; d = dst[gw]; }
    else              { s = d = gw - N_EDGES; }
    int h8 = lane & 7;
    float a = g_asrc1[s * 8 + h8] + g_adst1[d * 8 + h8];
    a = lrelu(a);
    float ex = __expf(a - g_amax1[d * 8 + h8]);
    if (lane < 8) atomicAdd(&g_denom1[d * 8 + lane], ex);
    float wgt = __shfl_sync(0xffffffffu, ex, lane >> 2);
    float4 hv = *(const float4*)&g_h1[s * 128 + lane * 4];
    red_add_v4(&g_accum1[d * 128 + lane * 4],
               make_float4(hv.x * wgt, hv.y * wgt, hv.z * wgt, hv.w * wgt));
}

// ---------------- finalize layer1: hrelu = relu(accum/denom + bias1) ---------
__global__ void final1_kernel(const float* __restrict__ bias) {
    int i = blockIdx.x * blockDim.x + threadIdx.x;
    if (i >= N_NODES * 32) return;
    int e = i * 4;
    int n = e >> 7, j = e & 127, h = j >> 4;
    float inv = 1.0f / g_denom1[n * 8 + h];
    float4 a = *(const float4*)&g_accum1[e];
    float4 b = *(const float4*)&bias[j];
    float4 v;
    v.x = fmaxf(a.x * inv + b.x, 0.0f);
    v.y = fmaxf(a.y * inv + b.y, 0.0f);
    v.z = fmaxf(a.z * inv + b.z, 0.0f);
    v.w = fmaxf(a.w * inv + b.w, 0.0f);
    *(float4*)&g_hrelu[e] = v;
}

// ---------------- GEMM2 (+ fused a_src2/a_dst2): h2 = hrelu @ W2 -------------
__global__ __launch_bounds__(256) void gemm2_kernel(const float* __restrict__ W2,
                                                    const float* __restrict__ att_s,
                                                    const float* __restrict__ att_d) {
    __shared__ float Ws[128 * 16];
    __shared__ float Hs[16][128];
    int tid = threadIdx.x;
    int base = blockIdx.x * 16;
    for (int i = tid; i < 128 * 16; i += 256) Ws[i] = W2[i];
    for (int i = tid; i < 16 * 128; i += 256) {
        int r = i >> 7, c = i & 127;
        int gr = base + r;
        Hs[r][c] = (gr < N_NODES) ? g_hrelu[gr * 128 + c] : 0.0f;
    }
    __syncthreads();
    int ty = tid >> 4, tx = tid & 15;
    float sum = 0.0f;
#pragma unroll 8
    for (int k = 0; k < 128; k++) sum += Hs[ty][k] * Ws[k * 16 + tx];
    float ss = sum * att_s[tx];
    float sd = sum * att_d[tx];
#pragma unroll
    for (int off = 8; off; off >>= 1) {
        ss += __shfl_xor_sync(0xffffffffu, ss, off);
        sd += __shfl_xor_sync(0xffffffffu, sd, off);
    }
    int row = base + ty;
    if (row < N_NODES) {
        g_h2[row * 16 + tx] = sum;
        if (tx == 0) { g_asrc2[row] = ss; g_adst2[row] = sd; }
    }
}

// ---------------- layer2 edge pass A -----------------------------------------
__global__ void edgeA2_kernel(const int* __restrict__ src, const int* __restrict__ dst) {
    int e = blockIdx.x * blockDim.x + threadIdx.x;
    if (e >= E_TOT) return;
    int s, d;
    if (e < N_EDGES) { s = src[e]; d = dst[e]; }
    else             { s = d = e - N_EDGES; }
    float a = lrelu(g_asrc2[s] + g_adst2[d]);
    atomicMaxF(&g_amax2[d], a);
}

// ---------------- layer2 edge pass B -----------------------------------------
__global__ void edgeB2_kernel(const int* __restrict__ src, const int* __restrict__ dst) {
    int e = blockIdx.x * blockDim.x + threadIdx.x;
    if (e >= E_TOT) return;
    int s, d;
    if (e < N_EDGES) { s = src[e]; d = dst[e]; }
    else             { s = d = e - N_EDGES; }
    float a = lrelu(g_asrc2[s] + g_adst2[d]);
    float ex = __expf(a - g_amax2[d]);
    atomicAdd(&g_denom2[d], ex);
#pragma unroll
    for (int q = 0; q < 4; q++) {
        float4 hv = *(const float4*)&g_h2[s * 16 + q * 4];
        red_add_v4(&g_accum2[d * 16 + q * 4],
                   make_float4(hv.x * ex, hv.y * ex, hv.z * ex, hv.w * ex));
    }
}

// ---------------- finalize layer2 -> d_out -----------------------------------
__global__ void final2_kernel(const float* __restrict__ bias, float* __restrict__ out) {
    int i = blockIdx.x * blockDim.x + threadIdx.x;
    if (i >= N_NODES * 4) return;
    int e = i * 4;
    int n = e >> 4, j = e & 15;
    float inv = 1.0f / g_denom2[n];
    float4 a = *(const float4*)&g_accum2[e];
    float4 b = *(const float4*)&bias[j];
    float4 v;
    v.x = a.x * inv + b.x;
    v.y = a.y * inv + b.y;
    v.z = a.z * inv + b.z;
    v.w = a.w * inv + b.w;
    *(float4*)&out[e] = v;
}

// ---------------- launch ------------------------------------------------------
extern "C" void kernel_launch(void* const* d_in, const int* in_sizes, int n_in,
                              void* d_out, int out_size) {
    const float* x      = (const float*)d_in[0];
    const int*   ei     = (const int*)d_in[1];
    const float* W1     = (const float*)d_in[2];
    const float* att_s1 = (const float*)d_in[3];
    const float* att_d1 = (const float*)d_in[4];
    const float* b1     = (const float*)d_in[5];
    const float* W2     = (const float*)d_in[6];
    const float* att_s2 = (const float*)d_in[7];
    const float* att_d2 = (const float*)d_in[8];
    const float* b2     = (const float*)d_in[9];
    float* out = (float*)d_out;
    const int* src = ei;
    const int* dst = ei + N_EDGES;

    init_kernel<<<1024, 256>>>();
    gemm1_kernel<<<(N_NODES + 127) / 128, 256>>>(x, W1);
    att1_kernel<<<(N_NODES * 32 + 255) / 256, 256>>>(att_s1, att_d1);
    edgeA1_kernel<<<(E_TOT + 255) / 256, 256>>>(src, dst);
    edgeB1_kernel<<<(E_TOT + 7) / 8, 256>>>(src, dst);
    final1_kernel<<<(N_NODES * 32 + 255) / 256, 256>>>(b1);
    gemm2_kernel<<<(N_NODES + 15) / 16, 256>>>(W2, att_s2, att_d2);
    edgeA2_kernel<<<(E_TOT + 255) / 256, 256>>>(src, dst);
    edgeB2_kernel<<<(E_TOT + 255) / 256, 256>>>(src, dst);
    final2_kernel<<<(N_NODES * 4 + 255) / 256, 256>>>(b2, out);
}

// round 2
// speedup vs baseline: 2.0007x; 2.0007x over previous
#include <cuda_runtime.h>

#define N_NODES 50000
#define N_EDGES 1600000
#define E_TOT   (N_EDGES + N_NODES)
#define IN_C    256
#define HID_C   128
#define OUT_C   16
#define HEADS   8
#define NBLK_SCAN 49   // ceil(50000/1024)

// ---------------- scratch (device globals; no allocation allowed) ------------
__device__ __align__(256) float g_h1[N_NODES * HID_C];
__device__ __align__(256) float g_asrc1[N_NODES * HEADS];
__device__ __align__(256) float g_adst1[N_NODES * HEADS];
__device__ __align__(256) float g_hrelu[N_NODES * HID_C];
__device__ __align__(256) float g_h2[N_NODES * OUT_C];
__device__ __align__(256) float g_asrc2[N_NODES];
__device__ __align__(256) float g_adst2[N_NODES];
__device__ __align__(256) int   g_deg[N_NODES];
__device__ __align__(256) int   g_off[N_NODES + 1];
__device__ __align__(256) int   g_cursor[N_NODES];
__device__ __align__(256) int   g_part[64];
__device__ __align__(256) int   g_csr_src[E_TOT];

__device__ __forceinline__ float lrelu(float a) {
    return a > 0.0f ? a : 0.2f * a;
}

// ---------------- CSR build ---------------------------------------------------
__global__ void zero_deg_kernel() {
    int i = blockIdx.x * blockDim.x + threadIdx.x;
    if (i < N_NODES) g_deg[i] = 0;
}

__global__ void count_kernel(const int* __restrict__ dst) {
    int e = blockIdx.x * blockDim.x + threadIdx.x;
    if (e >= E_TOT) return;
    int d = (e < N_EDGES) ? dst[e] : e - N_EDGES;
    atomicAdd(&g_deg[d], 1);
}

__global__ void scanA_kernel() {   // 49 blocks x 256 threads: block partial sums
    __shared__ int sh[8];
    int b = blockIdx.x, t = threadIdx.x;
    int base = b * 1024 + t * 4;
    int s = 0;
#pragma unroll
    for (int k = 0; k < 4; k++) { int i = base + k; if (i < N_NODES) s += g_deg[i]; }
#pragma unroll
    for (int o = 16; o; o >>= 1) s += __shfl_xor_sync(0xffffffffu, s, o);
    if ((t & 31) == 0) sh[t >> 5] = s;
    __syncthreads();
    if (t < 8) {
        int v = sh[t];
#pragma unroll
        for (int o = 4; o; o >>= 1) v += __shfl_xor_sync(0xffffffffu, v, o);
        if (t == 0) g_part[b] = v;
    }
}

__global__ void scanB_kernel() {   // 1 block x 64 threads: scan the partials
    int t = threadIdx.x;
    int orig = (t < NBLK_SCAN) ? g_part[t] : 0;
    int v = orig;
    int lane = t & 31, w = t >> 5;
#pragma unroll
    for (int o = 1; o < 32; o <<= 1) {
        int u = __shfl_up_sync(0xffffffffu, v, o);
        if (lane >= o) v += u;
    }
    __shared__ int wsum;
    if (w == 0 && lane == 31) wsum = v;
    __syncthreads();
    if (w == 1) v += wsum;
    if (t < NBLK_SCAN) g_part[t] = v - orig;   // exclusive
    if (t == 0) g_off[N_NODES] = E_TOT;
}

__global__ void scanC_kernel() {   // 49 blocks x 256 threads: final offsets
    __shared__ int ws[8];
    int b = blockIdx.x, t = threadIdx.x;
    int base = b * 1024 + t * 4;
    int d0 = 0, d1 = 0, d2 = 0, d3 = 0;
    if (base + 0 < N_NODES) d0 = g_deg[base + 0];
    if (base + 1 < N_NODES) d1 = g_deg[base + 1];
    if (base + 2 < N_NODES) d2 = g_deg[base + 2];
    if (base + 3 < N_NODES) d3 = g_deg[base + 3];
    int tsum = d0 + d1 + d2 + d3;
    int lane = t & 31, w = t >> 5;
    int v = tsum;
#pragma unroll
    for (int o = 1; o < 32; o <<= 1) {
        int u = __shfl_up_sync(0xffffffffu, v, o);
        if (lane >= o) v += u;
    }
    if (lane == 31) ws[w] = v;
    __syncthreads();
    int woff = 0;
    for (int i = 0; i < w; i++) woff += ws[i];
    int excl = v - tsum + woff + g_part[b];
    int o0 = excl, o1 = o0 + d0, o2 = o1 + d1, o3 = o2 + d2;
    if (base + 0 < N_NODES) { g_off[base + 0] = o0; g_cursor[base + 0] = o0; }
    if (base + 1 < N_NODES) { g_off[base + 1] = o1; g_cursor[base + 1] = o1; }
    if (base + 2 < N_NODES) { g_off[base + 2] = o2; g_cursor[base + 2] = o2; }
    if (base + 3 < N_NODES) { g_off[base + 3] = o3; g_cursor[base + 3] = o3; }
}

__global__ void scatter_kernel(const int* __restrict__ src, const int* __restrict__ dst) {
    int e = blockIdx.x * blockDim.x + threadIdx.x;
    if (e >= E_TOT) return;
    int s, d;
    if (e < N_EDGES) { s = src[e]; d = dst[e]; }
    else             { s = d = e - N_EDGES; }
    int pos = atomicAdd(&g_cursor[d], 1);
    g_csr_src[pos] = s;
}

// ---------------- GEMM1: h1 = x @ W1  (50000x256 @ 256x128) ------------------
__global__ __launch_bounds__(256) void gemm1_kernel(const float* __restrict__ A,
                                                    const float* __restrict__ B) {
    __shared__ float As[8][128];
    __shared__ float Bs[8][128];
    const int M = N_NODES, N = 128, K = 256;
    int rowBase = blockIdx.x * 128;
    int tid = threadIdx.x;
    int trow = tid >> 4;
    int tcol = tid & 15;
    float acc[8][8] = {};
    int aRow = tid >> 1;
    int aCol = (tid & 1) * 4;
    int bRow = tid >> 5;
    int bCol = (tid & 31) * 4;

    for (int k0 = 0; k0 < K; k0 += 8) {
        float4 av = make_float4(0.f, 0.f, 0.f, 0.f);
        int gr = rowBase + aRow;
        if (gr < M) av = *(const float4*)&A[(long)gr * K + k0 + aCol];
        As[aCol + 0][aRow] = av.x;
        As[aCol + 1][aRow] = av.y;
        As[aCol + 2][aRow] = av.z;
        As[aCol + 3][aRow] = av.w;
        *(float4*)&Bs[bRow][bCol] = *(const float4*)&B[(k0 + bRow) * N + bCol];
        __syncthreads();
#pragma unroll
        for (int k = 0; k < 8; k++) {
            float ra[8], rb[8];
#pragma unroll
            for (int i = 0; i < 8; i++) ra[i] = As[k][trow * 8 + i];
#pragma unroll
            for (int j = 0; j < 8; j++) rb[j] = Bs[k][tcol * 8 + j];
#pragma unroll
            for (int i = 0; i < 8; i++)
#pragma unroll
                for (int j = 0; j < 8; j++) acc[i][j] += ra[i] * rb[j];
        }
        __syncthreads();
    }
#pragma unroll
    for (int i = 0; i < 8; i++) {
        int r = rowBase + trow * 8 + i;
        if (r < M) {
#pragma unroll
            for (int j = 0; j < 8; j += 4) {
                float4 v = make_float4(acc[i][j], acc[i][j + 1], acc[i][j + 2], acc[i][j + 3]);
                *(float4*)&g_h1[r * 128 + tcol * 8 + j] = v;
            }
        }
    }
}

// ---------------- a_src1 / a_dst1 per node (warp per node) -------------------
__global__ void att1_kernel(const float* __restrict__ att_s,
                            const float* __restrict__ att_d) {
    int w = (blockIdx.x * blockDim.x + threadIdx.x) >> 5;
    int lane = threadIdx.x & 31;
    if (w >= N_NODES) return;
    int h = lane >> 2, q = lane & 3;
    float4 hv = *(const float4*)&g_h1[w * 128 + lane * 4];
    float4 as = *(const float4*)&att_s[h * 16 + q * 4];
    float4 ad = *(const float4*)&att_d[h * 16 + q * 4];
    float ps = hv.x * as.x + hv.y * as.y + hv.z * as.z + hv.w * as.w;
    float pd = hv.x * ad.x + hv.y * ad.y + hv.z * ad.z + hv.w * ad.w;
    ps += __shfl_xor_sync(0xffffffffu, ps, 1);
    ps += __shfl_xor_sync(0xffffffffu, ps, 2);
    pd += __shfl_xor_sync(0xffffffffu, pd, 1);
    pd += __shfl_xor_sync(0xffffffffu, pd, 2);
    if (q == 0) {
        g_asrc1[w * 8 + h] = ps;
        g_adst1[w * 8 + h] = pd;
    }
}

// ---------------- layer1 gather: warp per dst node ---------------------------
// lane l -> channels 4l..4l+3, head l>>2. No max-shift (exact softmax algebra).
__global__ __launch_bounds__(256) void gather1_kernel(const float* __restrict__ bias) {
    int n = (blockIdx.x * blockDim.x + threadIdx.x) >> 5;
    int lane = threadIdx.x & 31;
    if (n >= N_NODES) return;
    int h = lane >> 2;
    float adv = g_adst1[n * 8 + h];
    int j = g_off[n], jend = g_off[n + 1];
    float4 acc = make_float4(0.f, 0.f, 0.f, 0.f);
    float dsum = 0.0f;
    for (; j + 1 < jend; j += 2) {
        int sa = g_csr_src[j];
        int sb = g_csr_src[j + 1];
        float ea = __expf(lrelu(g_asrc1[sa * 8 + h] + adv));
        float eb = __expf(lrelu(g_asrc1[sb * 8 + h] + adv));
        float4 ha = *(const float4*)&g_h1[sa * 128 + lane * 4];
        float4 hb = *(const float4*)&g_h1[sb * 128 + lane * 4];
        acc.x += ha.x * ea + hb.x * eb;
        acc.y += ha.y * ea + hb.y * eb;
        acc.z += ha.z * ea + hb.z * eb;
        acc.w += ha.w * ea + hb.w * eb;
        dsum += ea + eb;
    }
    if (j < jend) {
        int sa = g_csr_src[j];
        float ea = __expf(lrelu(g_asrc1[sa * 8 + h] + adv));
        float4 ha = *(const float4*)&g_h1[sa * 128 + lane * 4];
        acc.x += ha.x * ea;
        acc.y += ha.y * ea;
        acc.z += ha.z * ea;
        acc.w += ha.w * ea;
        dsum += ea;
    }
    float inv = 1.0f / dsum;
    float4 b = *(const float4*)&bias[lane * 4];
    float4 v;
    v.x = fmaxf(acc.x * inv + b.x, 0.0f);
    v.y = fmaxf(acc.y * inv + b.y, 0.0f);
    v.z = fmaxf(acc.z * inv + b.z, 0.0f);
    v.w = fmaxf(acc.w * inv + b.w, 0.0f);
    *(float4*)&g_hrelu[n * 128 + lane * 4] = v;
}

// ---------------- GEMM2 (+ fused a_src2/a_dst2): h2 = hrelu @ W2 -------------
__global__ __launch_bounds__(256) void gemm2_kernel(const float* __restrict__ W2,
                                                    const float* __restrict__ att_s,
                                                    const float* __restrict__ att_d) {
    __shared__ float Ws[128 * 16];
    __shared__ float Hs[16][128];
    int tid = threadIdx.x;
    int base = blockIdx.x * 16;
    for (int i = tid; i < 128 * 16; i += 256) Ws[i] = W2[i];
    for (int i = tid; i < 16 * 128; i += 256) {
        int r = i >> 7, c = i & 127;
        int gr = base + r;
        Hs[r][c] = (gr < N_NODES) ? g_hrelu[gr * 128 + c] : 0.0f;
    }
    __syncthreads();
    int ty = tid >> 4, tx = tid & 15;
    float sum = 0.0f;
#pragma unroll 8
    for (int k = 0; k < 128; k++) sum += Hs[ty][k] * Ws[k * 16 + tx];
    float ss = sum * att_s[tx];
    float sd = sum * att_d[tx];
#pragma unroll
    for (int off = 8; off; off >>= 1) {
        ss += __shfl_xor_sync(0xffffffffu, ss, off);
        sd += __shfl_xor_sync(0xffffffffu, sd, off);
    }
    int row = base + ty;
    if (row < N_NODES) {
        g_h2[row * 16 + tx] = sum;
        if (tx == 0) { g_asrc2[row] = ss; g_adst2[row] = sd; }
    }
}

// ---------------- layer2 gather: 4 lanes per dst node ------------------------
__global__ __launch_bounds__(256) void gather2_kernel(const float* __restrict__ bias,
                                                      float* __restrict__ out) {
    int gid = blockIdx.x * blockDim.x + threadIdx.x;
    int n = gid >> 2;
    int q = gid & 3;
    if (n >= N_NODES) return;
    float adv = g_adst2[n];
    int j = g_off[n], jend = g_off[n + 1];
    float4 acc = make_float4(0.f, 0.f, 0.f, 0.f);
    float dsum = 0.0f;
    for (; j + 1 < jend; j += 2) {
        int sa = g_csr_src[j];
        int sb = g_csr_src[j + 1];
        float ea = __expf(lrelu(g_asrc2[sa] + adv));
        float eb = __expf(lrelu(g_asrc2[sb] + adv));
        float4 ha = *(const float4*)&g_h2[sa * 16 + q * 4];
        float4 hb = *(const float4*)&g_h2[sb * 16 + q * 4];
        acc.x += ha.x * ea + hb.x * eb;
        acc.y += ha.y * ea + hb.y * eb;
        acc.z += ha.z * ea + hb.z * eb;
        acc.w += ha.w * ea + hb.w * eb;
        dsum += ea + eb;
    }
    if (j < jend) {
        int sa = g_csr_src[j];
        float ea = __expf(lrelu(g_asrc2[sa] + adv));
        float4 ha = *(const float4*)&g_h2[sa * 16 + q * 4];
        acc.x += ha.x * ea;
        acc.y += ha.y * ea;
        acc.z += ha.z * ea;
        acc.w += ha.w * ea;
        dsum += ea;
    }
    float inv = 1.0f / dsum;
    float4 b = *(const float4*)&bias[q * 4];
    float4 v;
    v.x = acc.x * inv + b.x;
    v.y = acc.y * inv + b.y;
    v.z = acc.z * inv + b.z;
    v.w = acc.w * inv + b.w;
    *(float4*)&out[n * 16 + q * 4] = v;
}

// ---------------- launch ------------------------------------------------------
extern "C" void kernel_launch(void* const* d_in, const int* in_sizes, int n_in,
                              void* d_out, int out_size) {
    const float* x      = (const float*)d_in[0];
    const int*   ei     = (const int*)d_in[1];
    const float* W1     = (const float*)d_in[2];
    const float* att_s1 = (const float*)d_in[3];
    const float* att_d1 = (const float*)d_in[4];
    const float* b1     = (const float*)d_in[5];
    const float* W2     = (const float*)d_in[6];
    const float* att_s2 = (const float*)d_in[7];
    const float* att_d2 = (const float*)d_in[8];
    const float* b2     = (const float*)d_in[9];
    float* out = (float*)d_out;
    const int* src = ei;
    const int* dst = ei + N_EDGES;

    // CSR build (by destination)
    zero_deg_kernel<<<(N_NODES + 255) / 256, 256>>>();
    count_kernel<<<(E_TOT + 255) / 256, 256>>>(dst);
    scanA_kernel<<<NBLK_SCAN, 256>>>();
    scanB_kernel<<<1, 64>>>();
    scanC_kernel<<<NBLK_SCAN, 256>>>();
    scatter_kernel<<<(E_TOT + 255) / 256, 256>>>(src, dst);

    // layer 1
    gemm1_kernel<<<(N_NODES + 127) / 128, 256>>>(x, W1);
    att1_kernel<<<(N_NODES * 32 + 255) / 256, 256>>>(att_s1, att_d1);
    gather1_kernel<<<(N_NODES * 32 + 255) / 256, 256>>>(b1);

    // layer 2
    gemm2_kernel<<<(N_NODES + 15) / 16, 256>>>(W2, att_s2, att_d2);
    gather2_kernel<<<(N_NODES * 4 + 255) / 256, 256>>>(b2, out);
}

// round 3
// speedup vs baseline: 2.1097x; 1.0544x over previous
#include <cuda_runtime.h>

#define N_NODES 50000
#define N_EDGES 1600000
#define E_TOT   (N_EDGES + N_NODES)
#define IN_C    256
#define HID_C   128
#define OUT_C   16
#define HEADS   8
#define NBLK_SCAN 49   // ceil(50000/1024)

// ---------------- scratch (device globals; no allocation allowed) ------------
__device__ __align__(256) float g_h1[N_NODES * HID_C];
__device__ __align__(256) float g_asrc1[N_NODES * HEADS];
__device__ __align__(256) float g_adst1[N_NODES * HEADS];
__device__ __align__(256) float g_hrelu[N_NODES * HID_C];
__device__ __align__(256) float g_h2[N_NODES * OUT_C];
__device__ __align__(256) float g_asrc2[N_NODES];
__device__ __align__(256) float g_adst2[N_NODES];
__device__ __align__(256) int   g_deg[N_NODES];
__device__ __align__(256) int   g_off[N_NODES + 1];
__device__ __align__(256) int   g_cursor[N_NODES];
__device__ __align__(256) int   g_part[64];
__device__ __align__(256) int   g_csr_src[E_TOT];

__device__ __forceinline__ float lrelu(float a) {
    return a > 0.0f ? a : 0.2f * a;
}

__device__ __forceinline__ unsigned to_tf32(float f) {
    unsigned u;
    asm("cvt.rna.tf32.f32 %0, %1;" : "=r"(u) : "f"(f));
    return u;
}

__device__ __forceinline__ void mma_tf32(float* d, const unsigned* a, const unsigned* b) {
    asm volatile(
        "mma.sync.aligned.m16n8k8.row.col.f32.tf32.tf32.f32 "
        "{%0,%1,%2,%3}, {%4,%5,%6,%7}, {%8,%9}, {%0,%1,%2,%3};\n"
        : "+f"(d[0]), "+f"(d[1]), "+f"(d[2]), "+f"(d[3])
        : "r"(a[0]), "r"(a[1]), "r"(a[2]), "r"(a[3]), "r"(b[0]), "r"(b[1]));
}

// ---------------- CSR build ---------------------------------------------------
__global__ void zero_deg_kernel() {
    int i = blockIdx.x * blockDim.x + threadIdx.x;
    if (i < N_NODES) g_deg[i] = 0;
}

__global__ void count_kernel(const int* __restrict__ dst) {
    int e = blockIdx.x * blockDim.x + threadIdx.x;
    if (e >= E_TOT) return;
    int d = (e < N_EDGES) ? dst[e] : e - N_EDGES;
    atomicAdd(&g_deg[d], 1);
}

__global__ void scanA_kernel() {   // 49 blocks x 256 threads: block partial sums
    __shared__ int sh[8];
    int b = blockIdx.x, t = threadIdx.x;
    int base = b * 1024 + t * 4;
    int s = 0;
#pragma unroll
    for (int k = 0; k < 4; k++) { int i = base + k; if (i < N_NODES) s += g_deg[i]; }
#pragma unroll
    for (int o = 16; o; o >>= 1) s += __shfl_xor_sync(0xffffffffu, s, o);
    if ((t & 31) == 0) sh[t >> 5] = s;
    __syncthreads();
    if (t < 8) {
        int v = sh[t];
#pragma unroll
        for (int o = 4; o; o >>= 1) v += __shfl_xor_sync(0xffffffffu, v, o);
        if (t == 0) g_part[b] = v;
    }
}

__global__ void scanC_kernel() {   // final offsets; scans the 49 partials inline
    __shared__ int ws[8];
    __shared__ int s_pre;
    int b = blockIdx.x, t = threadIdx.x;
    int lane = t & 31, w = t >> 5;
    if (w == 0) {   // warp 0: exclusive prefix of block partials
        int v = 0;
        if (lane < b && lane < NBLK_SCAN) v = g_part[lane];
        if (lane + 32 < b && lane + 32 < NBLK_SCAN) v += g_part[lane + 32];
#pragma unroll
        for (int o = 16; o; o >>= 1) v += __shfl_xor_sync(0xffffffffu, v, o);
        if (lane == 0) s_pre = v;
    }
    int base = b * 1024 + t * 4;
    int d0 = 0, d1 = 0, d2 = 0, d3 = 0;
    if (base + 0 < N_NODES) d0 = g_deg[base + 0];
    if (base + 1 < N_NODES) d1 = g_deg[base + 1];
    if (base + 2 < N_NODES) d2 = g_deg[base + 2];
    if (base + 3 < N_NODES) d3 = g_deg[base + 3];
    int tsum = d0 + d1 + d2 + d3;
    int v = tsum;
#pragma unroll
    for (int o = 1; o < 32; o <<= 1) {
        int u = __shfl_up_sync(0xffffffffu, v, o);
        if (lane >= o) v += u;
    }
    if (lane == 31) ws[w] = v;
    __syncthreads();
    int woff = 0;
    for (int i = 0; i < w; i++) woff += ws[i];
    int excl = v - tsum + woff + s_pre;
    int o0 = excl, o1 = o0 + d0, o2 = o1 + d1, o3 = o2 + d2;
    if (base + 0 < N_NODES) { g_off[base + 0] = o0; g_cursor[base + 0] = o0; }
    if (base + 1 < N_NODES) { g_off[base + 1] = o1; g_cursor[base + 1] = o1; }
    if (base + 2 < N_NODES) { g_off[base + 2] = o2; g_cursor[base + 2] = o2; }
    if (base + 3 < N_NODES) { g_off[base + 3] = o3; g_cursor[base + 3] = o3; }
    if (b == 0 && t == 0) g_off[N_NODES] = E_TOT;
}

__global__ void scatter_kernel(const int* __restrict__ src, const int* __restrict__ dst) {
    int e = blockIdx.x * blockDim.x + threadIdx.x;
    if (e >= E_TOT) return;
    int s, d;
    if (e < N_EDGES) { s = src[e]; d = dst[e]; }
    else             { s = d = e - N_EDGES; }
    int pos = atomicAdd(&g_cursor[d], 1);
    g_csr_src[pos] = s;
}

// ---------------- GEMM1 (tf32 tensor cores): h1 = x @ W1 ---------------------
// BM=128 BN=128 BK=16, 256 threads (8 warps: 4x2), warp tile 32x64.
// smem permuted so every fragment load is a conflict-free LDS.64:
//   idx(elem r|n, k) = ((s*128 + r)*4 + kq)*2 + sel  with k = s*8 + sel*4 + kq
__global__ __launch_bounds__(256) void gemm1_kernel(const float* __restrict__ A,
                                                    const float* __restrict__ B) {
    __shared__ float As[2][2048];
    __shared__ float Bs[2][2048];
    const int M = N_NODES;
    int rowBase = blockIdx.x * 128;
    int tid = threadIdx.x;
    int lane = tid & 31;
    int warpId = tid >> 5;
    int wmRow = (warpId >> 1) * 32;
    int wnCol = (warpId & 1) * 64;

    float acc[2][8][4];
#pragma unroll
    for (int i = 0; i < 2; i++)
#pragma unroll
        for (int j = 0; j < 8; j++)
#pragma unroll
            for (int q = 0; q < 4; q++) acc[i][j][q] = 0.0f;

    // --- prologue: load chunk 0 into smem buffer 0 ---
    {
#pragma unroll
        for (int p = 0; p < 2; p++) {
            int fidx = tid + p * 256;
            // A: 128 rows x 16 k = 512 float4
            int arow = fidx >> 2;
            int kc = (fidx & 3) * 4;
            int gr = rowBase + arow;
            float4 av = make_float4(0.f, 0.f, 0.f, 0.f);
            if (gr < M) av = *(const float4*)&A[(long)gr * IN_C + kc];
            float ae[4] = { av.x, av.y, av.z, av.w };
#pragma unroll
            for (int i = 0; i < 4; i++) {
                int kl = kc + i;
                As[0][(((kl >> 3) * 128 + arow) * 4 + (kl & 3)) * 2 + ((kl >> 2) & 1)] = ae[i];
            }
            // B: 16 k x 128 n = 512 float4
            int krow = fidx >> 5;
            int n0 = (fidx & 31) * 4;
            float4 bv = *(const float4*)&B[krow * 128 + n0];
            float be[4] = { bv.x, bv.y, bv.z, bv.w };
#pragma unroll
            for (int i = 0; i < 4; i++) {
                Bs[0][(((krow >> 3) * 128 + n0 + i) * 4 + (krow & 3)) * 2 + ((krow >> 2) & 1)] = be[i];
            }
        }
    }
    __syncthreads();

    float4 ra[2], rb[2];
    for (int c = 0; c < 16; c++) {
        int buf = c & 1;
        // stage next chunk's global loads
        if (c < 15) {
            int kbase = (c + 1) * 16;
#pragma unroll
            for (int p = 0; p < 2; p++) {
                int fidx = tid + p * 256;
                int arow = fidx >> 2;
                int kc = (fidx & 3) * 4;
                int gr = rowBase + arow;
                ra[p] = make_float4(0.f, 0.f, 0.f, 0.f);
                if (gr < M) ra[p] = *(const float4*)&A[(long)gr * IN_C + kbase + kc];
                int krow = fidx >> 5;
                int n0 = (fidx & 31) * 4;
                rb[p] = *(const float4*)&B[(kbase + krow) * 128 + n0];
            }
        }
        // compute on current buffer
        const float2* As2 = (const float2*)As[buf];
        const float2* Bs2 = (const float2*)Bs[buf];
#pragma unroll
        for (int s = 0; s < 2; s++) {
            unsigned ua[2][4], ub[8][2];
#pragma unroll
            for (int mi = 0; mi < 2; mi++) {
                int rb_ = wmRow + mi * 16 + (lane >> 2);
                float2 lo = As2[(s * 128 + rb_) * 4 + (lane & 3)];        // (a0, a2)
                float2 hi = As2[(s * 128 + rb_ + 8) * 4 + (lane & 3)];    // (a1, a3)
                ua[mi][0] = to_tf32(lo.x);
                ua[mi][1] = to_tf32(hi.x);
                ua[mi][2] = to_tf32(lo.y);
                ua[mi][3] = to_tf32(hi.y);
            }
#pragma unroll
            for (int nj = 0; nj < 8; nj++) {
                int nb = wnCol + nj * 8 + (lane >> 2);
                float2 bb = Bs2[(s * 128 + nb) * 4 + (lane & 3)];         // (b0, b1)
                ub[nj][0] = to_tf32(bb.x);
                ub[nj][1] = to_tf32(bb.y);
            }
#pragma unroll
            for (int mi = 0; mi < 2; mi++)
#pragma unroll
                for (int nj = 0; nj < 8; nj++)
                    mma_tf32(acc[mi][nj], ua[mi], ub[nj]);
        }
        // commit staged loads into other buffer
        if (c < 15) {
            int nb_ = buf ^ 1;
#pragma unroll
            for (int p = 0; p < 2; p++) {
                int fidx = tid + p * 256;
                int arow = fidx >> 2;
                int kc = (fidx & 3) * 4;
                float ae[4] = { ra[p].x, ra[p].y, ra[p].z, ra[p].w };
#pragma unroll
                for (int i = 0; i < 4; i++) {
                    int kl = kc + i;
                    As[nb_][(((kl >> 3) * 128 + arow) * 4 + (kl & 3)) * 2 + ((kl >> 2) & 1)] = ae[i];
                }
                int krow = fidx >> 5;
                int n0 = (fidx & 31) * 4;
                float be[4] = { rb[p].x, rb[p].y, rb[p].z, rb[p].w };
#pragma unroll
                for (int i = 0; i < 4; i++) {
                    Bs[nb_][(((krow >> 3) * 128 + n0 + i) * 4 + (krow & 3)) * 2 + ((krow >> 2) & 1)] = be[i];
                }
            }
        }
        __syncthreads();
    }

    // epilogue: c0/c1 at (row, 2c), (row, 2c+1); c2/c3 at row+8
#pragma unroll
    for (int mi = 0; mi < 2; mi++) {
#pragma unroll
        for (int nj = 0; nj < 8; nj++) {
            int r0 = rowBase + wmRow + mi * 16 + (lane >> 2);
            int col = wnCol + nj * 8 + (lane & 3) * 2;
            if (r0 < M)
                *(float2*)&g_h1[r0 * 128 + col] = make_float2(acc[mi][nj][0], acc[mi][nj][1]);
            if (r0 + 8 < M)
                *(float2*)&g_h1[(r0 + 8) * 128 + col] = make_float2(acc[mi][nj][2], acc[mi][nj][3]);
        }
    }
}

// ---------------- a_src1 / a_dst1 per node (warp per node) -------------------
__global__ void att1_kernel(const float* __restrict__ att_s,
                            const float* __restrict__ att_d) {
    int w = (blockIdx.x * blockDim.x + threadIdx.x) >> 5;
    int lane = threadIdx.x & 31;
    if (w >= N_NODES) return;
    int h = lane >> 2, q = lane & 3;
    float4 hv = *(const float4*)&g_h1[w * 128 + lane * 4];
    float4 as = *(const float4*)&att_s[h * 16 + q * 4];
    float4 ad = *(const float4*)&att_d[h * 16 + q * 4];
    float ps = hv.x * as.x + hv.y * as.y + hv.z * as.z + hv.w * as.w;
    float pd = hv.x * ad.x + hv.y * ad.y + hv.z * ad.z + hv.w * ad.w;
    ps += __shfl_xor_sync(0xffffffffu, ps, 1);
    ps += __shfl_xor_sync(0xffffffffu, ps, 2);
    pd += __shfl_xor_sync(0xffffffffu, pd, 1);
    pd += __shfl_xor_sync(0xffffffffu, pd, 2);
    if (q == 0) {
        g_asrc1[w * 8 + h] = ps;
        g_adst1[w * 8 + h] = pd;
    }
}

// ---------------- layer1 gather: warp per dst node ---------------------------
__global__ __launch_bounds__(256) void gather1_kernel(const float* __restrict__ bias) {
    int n = (blockIdx.x * blockDim.x + threadIdx.x) >> 5;
    int lane = threadIdx.x & 31;
    if (n >= N_NODES) return;
    int h = lane >> 2;
    float adv = g_adst1[n * 8 + h];
    int j = g_off[n], jend = g_off[n + 1];
    float4 acc = make_float4(0.f, 0.f, 0.f, 0.f);
    float dsum = 0.0f;
    for (; j + 1 < jend; j += 2) {
        int sa = g_csr_src[j];
        int sb = g_csr_src[j + 1];
        float ea = __expf(lrelu(g_asrc1[sa * 8 + h] + adv));
        float eb = __expf(lrelu(g_asrc1[sb * 8 + h] + adv));
        float4 ha = *(const float4*)&g_h1[sa * 128 + lane * 4];
        float4 hb = *(const float4*)&g_h1[sb * 128 + lane * 4];
        acc.x += ha.x * ea + hb.x * eb;
        acc.y += ha.y * ea + hb.y * eb;
        acc.z += ha.z * ea + hb.z * eb;
        acc.w += ha.w * ea + hb.w * eb;
        dsum += ea + eb;
    }
    if (j < jend) {
        int sa = g_csr_src[j];
        float ea = __expf(lrelu(g_asrc1[sa * 8 + h] + adv));
        float4 ha = *(const float4*)&g_h1[sa * 128 + lane * 4];
        acc.x += ha.x * ea;
        acc.y += ha.y * ea;
        acc.z += ha.z * ea;
        acc.w += ha.w * ea;
        dsum += ea;
    }
    float inv = 1.0f / dsum;
    float4 b = *(const float4*)&bias[lane * 4];
    float4 v;
    v.x = fmaxf(acc.x * inv + b.x, 0.0f);
    v.y = fmaxf(acc.y * inv + b.y, 0.0f);
    v.z = fmaxf(acc.z * inv + b.z, 0.0f);
    v.w = fmaxf(acc.w * inv + b.w, 0.0f);
    *(float4*)&g_hrelu[n * 128 + lane * 4] = v;
}

// ---------------- GEMM2 (+ fused a_src2/a_dst2): h2 = hrelu @ W2 -------------
__global__ __launch_bounds__(256) void gemm2_kernel(const float* __restrict__ W2,
                                                    const float* __restrict__ att_s,
                                                    const float* __restrict__ att_d) {
    __shared__ float Ws[128 * 16];
    __shared__ float Hs[16][128];
    int tid = threadIdx.x;
    int base = blockIdx.x * 16;
    for (int i = tid; i < 128 * 16; i += 256) Ws[i] = W2[i];
    for (int i = tid; i < 16 * 128; i += 256) {
        int r = i >> 7, c = i & 127;
        int gr = base + r;
        Hs[r][c] = (gr < N_NODES) ? g_hrelu[gr * 128 + c] : 0.0f;
    }
    __syncthreads();
    int ty = tid >> 4, tx = tid & 15;
    float sum = 0.0f;
#pragma unroll 8
    for (int k = 0; k < 128; k++) sum += Hs[ty][k] * Ws[k * 16 + tx];
    float ss = sum * att_s[tx];
    float sd = sum * att_d[tx];
#pragma unroll
    for (int off = 8; off; off >>= 1) {
        ss += __shfl_xor_sync(0xffffffffu, ss, off);
        sd += __shfl_xor_sync(0xffffffffu, sd, off);
    }
    int row = base + ty;
    if (row < N_NODES) {
        g_h2[row * 16 + tx] = sum;
        if (tx == 0) { g_asrc2[row] = ss; g_adst2[row] = sd; }
    }
}

// ---------------- layer2 gather: 4 lanes per dst node ------------------------
__global__ __launch_bounds__(256) void gather2_kernel(const float* __restrict__ bias,
                                                      float* __restrict__ out) {
    int gid = blockIdx.x * blockDim.x + threadIdx.x;
    int n = gid >> 2;
    int q = gid & 3;
    if (n >= N_NODES) return;
    float adv = g_adst2[n];
    int j = g_off[n], jend = g_off[n + 1];
    float4 acc = make_float4(0.f, 0.f, 0.f, 0.f);
    float dsum = 0.0f;
    for (; j + 1 < jend; j += 2) {
        int sa = g_csr_src[j];
        int sb = g_csr_src[j + 1];
        float ea = __expf(lrelu(g_asrc2[sa] + adv));
        float eb = __expf(lrelu(g_asrc2[sb] + adv));
        float4 ha = *(const float4*)&g_h2[sa * 16 + q * 4];
        float4 hb = *(const float4*)&g_h2[sb * 16 + q * 4];
        acc.x += ha.x * ea + hb.x * eb;
        acc.y += ha.y * ea + hb.y * eb;
        acc.z += ha.z * ea + hb.z * eb;
        acc.w += ha.w * ea + hb.w * eb;
        dsum += ea + eb;
    }
    if (j < jend) {
        int sa = g_csr_src[j];
        float ea = __expf(lrelu(g_asrc2[sa] + adv));
        float4 ha = *(const float4*)&g_h2[sa * 16 + q * 4];
        acc.x += ha.x * ea;
        acc.y += ha.y * ea;
        acc.z += ha.z * ea;
        acc.w += ha.w * ea;
        dsum += ea;
    }
    float inv = 1.0f / dsum;
    float4 b = *(const float4*)&bias[q * 4];
    float4 v;
    v.x = acc.x * inv + b.x;
    v.y = acc.y * inv + b.y;
    v.z = acc.z * inv + b.z;
    v.w = acc.w * inv + b.w;
    *(float4*)&out[n * 16 + q * 4] = v;
}

// ---------------- launch ------------------------------------------------------
extern "C" void kernel_launch(void* const* d_in, const int* in_sizes, int n_in,
                              void* d_out, int out_size) {
    const float* x      = (const float*)d_in[0];
    const int*   ei     = (const int*)d_in[1];
    const float* W1     = (const float*)d_in[2];
    const float* att_s1 = (const float*)d_in[3];
    const float* att_d1 = (const float*)d_in[4];
    const float* b1     = (const float*)d_in[5];
    const float* W2     = (const float*)d_in[6];
    const float* att_s2 = (const float*)d_in[7];
    const float* att_d2 = (const float*)d_in[8];
    const float* b2     = (const float*)d_in[9];
    float* out = (float*)d_out;
    const int* src = ei;
    const int* dst = ei + N_EDGES;

    // CSR build (by destination)
    zero_deg_kernel<<<(N_NODES + 255) / 256, 256>>>();
    count_kernel<<<(E_TOT + 255) / 256, 256>>>(dst);
    scanA_kernel<<<NBLK_SCAN, 256>>>();
    scanC_kernel<<<NBLK_SCAN, 256>>>();
    scatter_kernel<<<(E_TOT + 255) / 256, 256>>>(src, dst);

    // layer 1
    gemm1_kernel<<<(N_NODES + 127) / 128, 256>>>(x, W1);
    att1_kernel<<<(N_NODES * 32 + 255) / 256, 256>>>(att_s1, att_d1);
    gather1_kernel<<<(N_NODES * 32 + 255) / 256, 256>>>(b1);

    // layer 2
    gemm2_kernel<<<(N_NODES + 15) / 16, 256>>>(W2, att_s2, att_d2);
    gather2_kernel<<<(N_NODES * 4 + 255) / 256, 256>>>(b2, out);
}

// round 4
// speedup vs baseline: 2.1443x; 1.0164x over previous
#include <cuda_runtime.h>
#include <cuda_fp16.h>

#define N_NODES 50000
#define N_EDGES 1600000
#define E_TOT   (N_EDGES + N_NODES)
#define IN_C    256
#define HID_C   128
#define OUT_C   16
#define HEADS   8
#define NBLK_SCAN 49   // ceil(50000/1024)

// ---------------- scratch (device globals; no allocation allowed) ------------
__device__ __align__(256) __half g_h1h[N_NODES * HID_C];     // fp16 messages L1
__device__ __align__(256) float  g_asrc1[N_NODES * HEADS];
__device__ __align__(256) float  g_adst1[N_NODES * HEADS];
__device__ __align__(256) __half g_hreluh[N_NODES * HID_C];  // fp16 layer1 out
__device__ __align__(256) __half g_h2h[N_NODES * OUT_C];     // fp16 messages L2
__device__ __align__(256) float  g_asrc2[N_NODES];
__device__ __align__(256) float  g_adst2[N_NODES];
__device__ __align__(256) int    g_deg[N_NODES];
__device__ __align__(256) int    g_off[N_NODES + 1];
__device__ __align__(256) int    g_cursor[N_NODES];
__device__ __align__(256) int    g_part[64];
__device__ __align__(256) int    g_csr_src[E_TOT];

__device__ __forceinline__ float lrelu(float a) {
    return a > 0.0f ? a : 0.2f * a;
}

__device__ __forceinline__ unsigned to_tf32(float f) {
    unsigned u;
    asm("cvt.rna.tf32.f32 %0, %1;" : "=r"(u) : "f"(f));
    return u;
}

__device__ __forceinline__ void mma_tf32(float* d, const unsigned* a, const unsigned* b) {
    asm volatile(
        "mma.sync.aligned.m16n8k8.row.col.f32.tf32.tf32.f32 "
        "{%0,%1,%2,%3}, {%4,%5,%6,%7}, {%8,%9}, {%0,%1,%2,%3};\n"
        : "+f"(d[0]), "+f"(d[1]), "+f"(d[2]), "+f"(d[3])
        : "r"(a[0]), "r"(a[1]), "r"(a[2]), "r"(a[3]), "r"(b[0]), "r"(b[1]));
}

// ---------------- CSR build ---------------------------------------------------
__global__ void zero_deg_kernel() {
    int i = blockIdx.x * blockDim.x + threadIdx.x;
    if (i < N_NODES) g_deg[i] = 0;
}

__global__ void count_kernel(const int* __restrict__ dst) {
    int e = blockIdx.x * blockDim.x + threadIdx.x;
    if (e >= E_TOT) return;
    int d = (e < N_EDGES) ? dst[e] : e - N_EDGES;
    atomicAdd(&g_deg[d], 1);
}

__global__ void scanA_kernel() {   // 49 blocks x 256 threads: block partial sums
    __shared__ int sh[8];
    int b = blockIdx.x, t = threadIdx.x;
    int base = b * 1024 + t * 4;
    int s = 0;
#pragma unroll
    for (int k = 0; k < 4; k++) { int i = base + k; if (i < N_NODES) s += g_deg[i]; }
#pragma unroll
    for (int o = 16; o; o >>= 1) s += __shfl_xor_sync(0xffffffffu, s, o);
    if ((t & 31) == 0) sh[t >> 5] = s;
    __syncthreads();
    if (t < 8) {
        int v = sh[t];
#pragma unroll
        for (int o = 4; o; o >>= 1) v += __shfl_xor_sync(0xffffffffu, v, o);
        if (t == 0) g_part[b] = v;
    }
}

__global__ void scanC_kernel() {   // final offsets; scans the 49 partials inline
    __shared__ int ws[8];
    __shared__ int s_pre;
    int b = blockIdx.x, t = threadIdx.x;
    int lane = t & 31, w = t >> 5;
    if (w == 0) {   // warp 0: exclusive prefix of block partials
        int v = 0;
        if (lane < b && lane < NBLK_SCAN) v = g_part[lane];
        if (lane + 32 < b && lane + 32 < NBLK_SCAN) v += g_part[lane + 32];
#pragma unroll
        for (int o = 16; o; o >>= 1) v += __shfl_xor_sync(0xffffffffu, v, o);
        if (lane == 0) s_pre = v;
    }
    int base = b * 1024 + t * 4;
    int d0 = 0, d1 = 0, d2 = 0, d3 = 0;
    if (base + 0 < N_NODES) d0 = g_deg[base + 0];
    if (base + 1 < N_NODES) d1 = g_deg[base + 1];
    if (base + 2 < N_NODES) d2 = g_deg[base + 2];
    if (base + 3 < N_NODES) d3 = g_deg[base + 3];
    int tsum = d0 + d1 + d2 + d3;
    int v = tsum;
#pragma unroll
    for (int o = 1; o < 32; o <<= 1) {
        int u = __shfl_up_sync(0xffffffffu, v, o);
        if (lane >= o) v += u;
    }
    if (lane == 31) ws[w] = v;
    __syncthreads();
    int woff = 0;
    for (int i = 0; i < w; i++) woff += ws[i];
    int excl = v - tsum + woff + s_pre;
    int o0 = excl, o1 = o0 + d0, o2 = o1 + d1, o3 = o2 + d2;
    if (base + 0 < N_NODES) { g_off[base + 0] = o0; g_cursor[base + 0] = o0; }
    if (base + 1 < N_NODES) { g_off[base + 1] = o1; g_cursor[base + 1] = o1; }
    if (base + 2 < N_NODES) { g_off[base + 2] = o2; g_cursor[base + 2] = o2; }
    if (base + 3 < N_NODES) { g_off[base + 3] = o3; g_cursor[base + 3] = o3; }
    if (b == 0 && t == 0) g_off[N_NODES] = E_TOT;
}

__global__ void scatter_kernel(const int* __restrict__ src, const int* __restrict__ dst) {
    int e = blockIdx.x * blockDim.x + threadIdx.x;
    if (e >= E_TOT) return;
    int s, d;
    if (e < N_EDGES) { s = src[e]; d = dst[e]; }
    else             { s = d = e - N_EDGES; }
    int pos = atomicAdd(&g_cursor[d], 1);
    g_csr_src[pos] = s;
}

// ---------------- GEMM1 (tf32 MMA) + fused att scores + fp16 h1 --------------
// BM=128 BN=128 BK=16, 256 threads (8 warps: 4x2), warp tile 32x64.
__global__ __launch_bounds__(256) void gemm1_kernel(const float* __restrict__ A,
                                                    const float* __restrict__ B,
                                                    const float* __restrict__ att_s,
                                                    const float* __restrict__ att_d) {
    __shared__ float As[2][2048];
    __shared__ float Bs[2][2048];
    const int M = N_NODES;
    int rowBase = blockIdx.x * 128;
    int tid = threadIdx.x;
    int lane = tid & 31;
    int warpId = tid >> 5;
    int wmRow = (warpId >> 1) * 32;
    int wnCol = (warpId & 1) * 64;

    float acc[2][8][4];
#pragma unroll
    for (int i = 0; i < 2; i++)
#pragma unroll
        for (int j = 0; j < 8; j++)
#pragma unroll
            for (int q = 0; q < 4; q++) acc[i][j][q] = 0.0f;

    // --- prologue: load chunk 0 into smem buffer 0 ---
#pragma unroll
    for (int p = 0; p < 2; p++) {
        int fidx = tid + p * 256;
        int arow = fidx >> 2;
        int kc = (fidx & 3) * 4;
        int gr = rowBase + arow;
        float4 av = make_float4(0.f, 0.f, 0.f, 0.f);
        if (gr < M) av = *(const float4*)&A[(long)gr * IN_C + kc];
        float ae[4] = { av.x, av.y, av.z, av.w };
#pragma unroll
        for (int i = 0; i < 4; i++) {
            int kl = kc + i;
            As[0][(((kl >> 3) * 128 + arow) * 4 + (kl & 3)) * 2 + ((kl >> 2) & 1)] = ae[i];
        }
        int krow = fidx >> 5;
        int n0 = (fidx & 31) * 4;
        float4 bv = *(const float4*)&B[krow * 128 + n0];
        float be[4] = { bv.x, bv.y, bv.z, bv.w };
#pragma unroll
        for (int i = 0; i < 4; i++) {
            Bs[0][(((krow >> 3) * 128 + n0 + i) * 4 + (krow & 3)) * 2 + ((krow >> 2) & 1)] = be[i];
        }
    }
    __syncthreads();

    float4 ra[2], rb[2];
    for (int c = 0; c < 16; c++) {
        int buf = c & 1;
        if (c < 15) {
            int kbase = (c + 1) * 16;
#pragma unroll
            for (int p = 0; p < 2; p++) {
                int fidx = tid + p * 256;
                int arow = fidx >> 2;
                int kc = (fidx & 3) * 4;
                int gr = rowBase + arow;
                ra[p] = make_float4(0.f, 0.f, 0.f, 0.f);
                if (gr < M) ra[p] = *(const float4*)&A[(long)gr * IN_C + kbase + kc];
                int krow = fidx >> 5;
                int n0 = (fidx & 31) * 4;
                rb[p] = *(const float4*)&B[(kbase + krow) * 128 + n0];
            }
        }
        const float2* As2 = (const float2*)As[buf];
        const float2* Bs2 = (const float2*)Bs[buf];
#pragma unroll
        for (int s = 0; s < 2; s++) {
            unsigned ua[2][4], ub[8][2];
#pragma unroll
            for (int mi = 0; mi < 2; mi++) {
                int rb_ = wmRow + mi * 16 + (lane >> 2);
                float2 lo = As2[(s * 128 + rb_) * 4 + (lane & 3)];
                float2 hi = As2[(s * 128 + rb_ + 8) * 4 + (lane & 3)];
                ua[mi][0] = to_tf32(lo.x);
                ua[mi][1] = to_tf32(hi.x);
                ua[mi][2] = to_tf32(lo.y);
                ua[mi][3] = to_tf32(hi.y);
            }
#pragma unroll
            for (int nj = 0; nj < 8; nj++) {
                int nb = wnCol + nj * 8 + (lane >> 2);
                float2 bb = Bs2[(s * 128 + nb) * 4 + (lane & 3)];
                ub[nj][0] = to_tf32(bb.x);
                ub[nj][1] = to_tf32(bb.y);
            }
#pragma unroll
            for (int mi = 0; mi < 2; mi++)
#pragma unroll
                for (int nj = 0; nj < 8; nj++)
                    mma_tf32(acc[mi][nj], ua[mi], ub[nj]);
        }
        if (c < 15) {
            int nb_ = buf ^ 1;
#pragma unroll
            for (int p = 0; p < 2; p++) {
                int fidx = tid + p * 256;
                int arow = fidx >> 2;
                int kc = (fidx & 3) * 4;
                float ae[4] = { ra[p].x, ra[p].y, ra[p].z, ra[p].w };
#pragma unroll
                for (int i = 0; i < 4; i++) {
                    int kl = kc + i;
                    As[nb_][(((kl >> 3) * 128 + arow) * 4 + (kl & 3)) * 2 + ((kl >> 2) & 1)] = ae[i];
                }
                int krow = fidx >> 5;
                int n0 = (fidx & 31) * 4;
                float be[4] = { rb[p].x, rb[p].y, rb[p].z, rb[p].w };
#pragma unroll
                for (int i = 0; i < 4; i++) {
                    Bs[nb_][(((krow >> 3) * 128 + n0 + i) * 4 + (krow & 3)) * 2 + ((krow >> 2) & 1)] = be[i];
                }
            }
        }
        __syncthreads();
    }

    // ---- epilogue 1: fp16 h1 stores ----
#pragma unroll
    for (int mi = 0; mi < 2; mi++) {
#pragma unroll
        for (int nj = 0; nj < 8; nj++) {
            int r0 = rowBase + wmRow + mi * 16 + (lane >> 2);
            int col = wnCol + nj * 8 + (lane & 3) * 2;
            if (r0 < M)
                *(__half2*)&g_h1h[r0 * 128 + col] = __floats2half2_rn(acc[mi][nj][0], acc[mi][nj][1]);
            if (r0 + 8 < M)
                *(__half2*)&g_h1h[(r0 + 8) * 128 + col] = __floats2half2_rn(acc[mi][nj][2], acc[mi][nj][3]);
        }
    }

    // ---- epilogue 2: fused attention scores (per-head dots) ----
    // s_part[mi][rowhalf][head-within-warp], warp covers heads hbase..hbase+3
    float s_part[2][2][4], d_part[2][2][4];
#pragma unroll
    for (int mi = 0; mi < 2; mi++)
#pragma unroll
        for (int r = 0; r < 2; r++)
#pragma unroll
            for (int hh = 0; hh < 4; hh++) { s_part[mi][r][hh] = 0.f; d_part[mi][r][hh] = 0.f; }

#pragma unroll
    for (int mi = 0; mi < 2; mi++) {
#pragma unroll
        for (int nj = 0; nj < 8; nj++) {
            int hh = nj >> 1;
            int ch0 = wnCol + nj * 8 + (lane & 3) * 2;
            float as0 = att_s[ch0], as1 = att_s[ch0 + 1];
            float ad0 = att_d[ch0], ad1 = att_d[ch0 + 1];
            s_part[mi][0][hh] += acc[mi][nj][0] * as0 + acc[mi][nj][1] * as1;
            d_part[mi][0][hh] += acc[mi][nj][0] * ad0 + acc[mi][nj][1] * ad1;
            s_part[mi][1][hh] += acc[mi][nj][2] * as0 + acc[mi][nj][3] * as1;
            d_part[mi][1][hh] += acc[mi][nj][2] * ad0 + acc[mi][nj][3] * ad1;
        }
    }
    // reduce over the 4 lanes of each quad (lane&3)
#pragma unroll
    for (int mi = 0; mi < 2; mi++)
#pragma unroll
        for (int r = 0; r < 2; r++)
#pragma unroll
            for (int hh = 0; hh < 4; hh++) {
                float vs = s_part[mi][r][hh], vd = d_part[mi][r][hh];
                vs += __shfl_xor_sync(0xffffffffu, vs, 1);
                vs += __shfl_xor_sync(0xffffffffu, vs, 2);
                vd += __shfl_xor_sync(0xffffffffu, vd, 1);
                vd += __shfl_xor_sync(0xffffffffu, vd, 2);
                s_part[mi][r][hh] = vs;
                d_part[mi][r][hh] = vd;
            }
    if ((lane & 3) == 0) {
        int hbase = wnCol >> 4;   // 0 or 4
#pragma unroll
        for (int mi = 0; mi < 2; mi++) {
            int r0 = rowBase + wmRow + mi * 16 + (lane >> 2);
#pragma unroll
            for (int r = 0; r < 2; r++) {
                int row = r0 + r * 8;
                if (row < M) {
#pragma unroll
                    for (int hh = 0; hh < 4; hh++) {
                        g_asrc1[row * 8 + hbase + hh] = s_part[mi][r][hh];
                        g_adst1[row * 8 + hbase + hh] = d_part[mi][r][hh];
                    }
                }
            }
        }
    }
}

// ---------------- layer1 gather: warp per dst node (fp16 messages) -----------
__global__ __launch_bounds__(256) void gather1_kernel(const float* __restrict__ bias) {
    int n = (blockIdx.x * blockDim.x + threadIdx.x) >> 5;
    int lane = threadIdx.x & 31;
    if (n >= N_NODES) return;
    int h = lane >> 2;
    float adv = g_adst1[n * 8 + h];
    int j = g_off[n], jend = g_off[n + 1];
    float4 acc = make_float4(0.f, 0.f, 0.f, 0.f);
    float dsum = 0.0f;
    for (; j + 1 < jend; j += 2) {
        int sa = g_csr_src[j];
        int sb = g_csr_src[j + 1];
        float ea = __expf(lrelu(g_asrc1[sa * 8 + h] + adv));
        float eb = __expf(lrelu(g_asrc1[sb * 8 + h] + adv));
        uint2 rwa = *(const uint2*)&g_h1h[sa * 128 + lane * 4];
        uint2 rwb = *(const uint2*)&g_h1h[sb * 128 + lane * 4];
        float2 a01 = __half22float2(*(__half2*)&rwa.x);
        float2 a23 = __half22float2(*(__half2*)&rwa.y);
        float2 b01 = __half22float2(*(__half2*)&rwb.x);
        float2 b23 = __half22float2(*(__half2*)&rwb.y);
        acc.x += a01.x * ea + b01.x * eb;
        acc.y += a01.y * ea + b01.y * eb;
        acc.z += a23.x * ea + b23.x * eb;
        acc.w += a23.y * ea + b23.y * eb;
        dsum += ea + eb;
    }
    if (j < jend) {
        int sa = g_csr_src[j];
        float ea = __expf(lrelu(g_asrc1[sa * 8 + h] + adv));
        uint2 rwa = *(const uint2*)&g_h1h[sa * 128 + lane * 4];
        float2 a01 = __half22float2(*(__half2*)&rwa.x);
        float2 a23 = __half22float2(*(__half2*)&rwa.y);
        acc.x += a01.x * ea;
        acc.y += a01.y * ea;
        acc.z += a23.x * ea;
        acc.w += a23.y * ea;
        dsum += ea;
    }
    float inv = 1.0f / dsum;
    float4 b = *(const float4*)&bias[lane * 4];
    __half2 o01 = __floats2half2_rn(fmaxf(acc.x * inv + b.x, 0.0f),
                                    fmaxf(acc.y * inv + b.y, 0.0f));
    __half2 o23 = __floats2half2_rn(fmaxf(acc.z * inv + b.z, 0.0f),
                                    fmaxf(acc.w * inv + b.w, 0.0f));
    uint2 ov;
    ov.x = *(unsigned*)&o01;
    ov.y = *(unsigned*)&o23;
    *(uint2*)&g_hreluh[n * 128 + lane * 4] = ov;
}

// ---------------- GEMM2 (+ fused a_src2/a_dst2): h2 = hrelu @ W2 -------------
__global__ __launch_bounds__(256) void gemm2_kernel(const float* __restrict__ W2,
                                                    const float* __restrict__ att_s,
                                                    const float* __restrict__ att_d) {
    __shared__ float Ws[128 * 16];
    __shared__ float Hs[16][128];
    int tid = threadIdx.x;
    int base = blockIdx.x * 16;
    for (int i = tid; i < 128 * 16; i += 256) Ws[i] = W2[i];
    for (int i = tid; i < 16 * 128; i += 256) {
        int r = i >> 7, c = i & 127;
        int gr = base + r;
        Hs[r][c] = (gr < N_NODES) ? __half2float(g_hreluh[gr * 128 + c]) : 0.0f;
    }
    __syncthreads();
    int ty = tid >> 4, tx = tid & 15;
    float sum = 0.0f;
#pragma unroll 8
    for (int k = 0; k < 128; k++) sum += Hs[ty][k] * Ws[k * 16 + tx];
    float ss = sum * att_s[tx];
    float sd = sum * att_d[tx];
#pragma unroll
    for (int off = 8; off; off >>= 1) {
        ss += __shfl_xor_sync(0xffffffffu, ss, off);
        sd += __shfl_xor_sync(0xffffffffu, sd, off);
    }
    int row = base + ty;
    if (row < N_NODES) {
        g_h2h[row * 16 + tx] = __float2half_rn(sum);
        if (tx == 0) { g_asrc2[row] = ss; g_adst2[row] = sd; }
    }
}

// ---------------- layer2 gather: 4 lanes per dst node (fp16 messages) --------
__global__ __launch_bounds__(256) void gather2_kernel(const float* __restrict__ bias,
                                                      float* __restrict__ out) {
    int gid = blockIdx.x * blockDim.x + threadIdx.x;
    int n = gid >> 2;
    int q = gid & 3;
    if (n >= N_NODES) return;
    float adv = g_adst2[n];
    int j = g_off[n], jend = g_off[n + 1];
    float4 acc = make_float4(0.f, 0.f, 0.f, 0.f);
    float dsum = 0.0f;
    for (; j + 1 < jend; j += 2) {
        int sa = g_csr_src[j];
        int sb = g_csr_src[j + 1];
        float ea = __expf(lrelu(g_asrc2[sa] + adv));
        float eb = __expf(lrelu(g_asrc2[sb] + adv));
        uint2 rwa = *(const uint2*)&g_h2h[sa * 16 + q * 4];
        uint2 rwb = *(const uint2*)&g_h2h[sb * 16 + q * 4];
        float2 a01 = __half22float2(*(__half2*)&rwa.x);
        float2 a23 = __half22float2(*(__half2*)&rwa.y);
        float2 b01 = __half22float2(*(__half2*)&rwb.x);
        float2 b23 = __half22float2(*(__half2*)&rwb.y);
        acc.x += a01.x * ea + b01.x * eb;
        acc.y += a01.y * ea + b01.y * eb;
        acc.z += a23.x * ea + b23.x * eb;
        acc.w += a23.y * ea + b23.y * eb;
        dsum += ea + eb;
    }
    if (j < jend) {
        int sa = g_csr_src[j];
        float ea = __expf(lrelu(g_asrc2[sa] + adv));
        uint2 rwa = *(const uint2*)&g_h2h[sa * 16 + q * 4];
        float2 a01 = __half22float2(*(__half2*)&rwa.x);
        float2 a23 = __half22float2(*(__half2*)&rwa.y);
        acc.x += a01.x * ea;
        acc.y += a01.y * ea;
        acc.z += a23.x * ea;
        acc.w += a23.y * ea;
        dsum += ea;
    }
    float inv = 1.0f / dsum;
    float4 b = *(const float4*)&bias[q * 4];
    float4 v;
    v.x = acc.x * inv + b.x;
    v.y = acc.y * inv + b.y;
    v.z = acc.z * inv + b.z;
    v.w = acc.w * inv + b.w;
    *(float4*)&out[n * 16 + q * 4] = v;
}

// ---------------- launch ------------------------------------------------------
extern "C" void kernel_launch(void* const* d_in, const int* in_sizes, int n_in,
                              void* d_out, int out_size) {
    const float* x      = (const float*)d_in[0];
    const int*   ei     = (const int*)d_in[1];
    const float* W1     = (const float*)d_in[2];
    const float* att_s1 = (const float*)d_in[3];
    const float* att_d1 = (const float*)d_in[4];
    const float* b1     = (const float*)d_in[5];
    const float* W2     = (const float*)d_in[6];
    const float* att_s2 = (const float*)d_in[7];
    const float* att_d2 = (const float*)d_in[8];
    const float* b2     = (const float*)d_in[9];
    float* out = (float*)d_out;
    const int* src = ei;
    const int* dst = ei + N_EDGES;

    // CSR build (by destination)
    zero_deg_kernel<<<(N_NODES + 255) / 256, 256>>>();
    count_kernel<<<(E_TOT + 255) / 256, 256>>>(dst);
    scanA_kernel<<<NBLK_SCAN, 256>>>();
    scanC_kernel<<<NBLK_SCAN, 256>>>();
    scatter_kernel<<<(E_TOT + 255) / 256, 256>>>(src, dst);

    // layer 1
    gemm1_kernel<<<(N_NODES + 127) / 128, 256>>>(x, W1, att_s1, att_d1);
    gather1_kernel<<<(N_NODES * 32 + 255) / 256, 256>>>(b1);

    // layer 2
    gemm2_kernel<<<(N_NODES + 15) / 16, 256>>>(W2, att_s2, att_d2);
    gather2_kernel<<<(N_NODES * 4 + 255) / 256, 256>>>(b2, out);
}